// round 1
// baseline (speedup 1.0000x reference)
#include <cuda_runtime.h>
#include <cuda_fp16.h>

#define LUT_D 33
#define NCELL (LUT_D * LUT_D * LUT_D)   // 35937

// Packed LUT: one 16B cell per (z,y,x0): fp16 {r0,g0,b0,r1,g1,b1,pad,pad}
// where index 1 is x0+1 clamped to 32. One LDG.128 fetches a full x-pair.
static __device__ __align__(16) uint4 g_cells[NCELL];

__global__ void repack_kernel(const float* __restrict__ lut) {
    int i = blockIdx.x * blockDim.x + threadIdx.x;
    if (i >= NCELL) return;
    int x0 = i % LUT_D;
    int x1 = min(x0 + 1, LUT_D - 1);
    int base = i - x0;
    float r0 = lut[0 * NCELL + base + x0];
    float g0 = lut[1 * NCELL + base + x0];
    float b0 = lut[2 * NCELL + base + x0];
    float r1 = lut[0 * NCELL + base + x1];
    float g1 = lut[1 * NCELL + base + x1];
    float b1 = lut[2 * NCELL + base + x1];
    __half2 h01 = __floats2half2_rn(r0, g0);
    __half2 h23 = __floats2half2_rn(b0, r1);
    __half2 h45 = __floats2half2_rn(g1, b1);
    uint4 v;
    v.x = reinterpret_cast<const unsigned int&>(h01);
    v.y = reinterpret_cast<const unsigned int&>(h23);
    v.z = reinterpret_cast<const unsigned int&>(h45);
    v.w = 0u;
    g_cells[i] = v;
}

__device__ __forceinline__ float3 lerp_cell(uint4 c, float fx) {
    __half2 h01 = reinterpret_cast<const __half2&>(c.x);  // (r0, g0)
    __half2 h23 = reinterpret_cast<const __half2&>(c.y);  // (b0, r1)
    __half2 h45 = reinterpret_cast<const __half2&>(c.z);  // (g1, b1)
    float2 f01 = __half22float2(h01);
    float2 f23 = __half22float2(h23);
    float2 f45 = __half22float2(h45);
    float r0 = f01.x, g0 = f01.y, b0 = f23.x;
    float r1 = f23.y, g1 = f45.x, b1 = f45.y;
    float3 o;
    o.x = fmaf(fx, r1 - r0, r0);
    o.y = fmaf(fx, g1 - g0, g0);
    o.z = fmaf(fx, b1 - b0, b0);
    return o;
}

__device__ __forceinline__ void sample_lut(float x, float y, float z,
                                           float& r, float& g, float& b) {
    const float S = 32.0f;
    x = fminf(fmaxf(x * S, 0.0f), S);
    y = fminf(fmaxf(y * S, 0.0f), S);
    z = fminf(fmaxf(z * S, 0.0f), S);
    int ix = (int)x;           // floor, x >= 0
    int iy = (int)y;
    int iz = (int)z;
    float fx = x - (float)ix;
    float fy = y - (float)iy;
    float fz = z - (float)iz;
    int iy1 = min(iy + 1, LUT_D - 1);
    int iz1 = min(iz + 1, LUT_D - 1);

    int row00 = (iz  * LUT_D + iy ) * LUT_D + ix;
    int row01 = (iz  * LUT_D + iy1) * LUT_D + ix;
    int row10 = (iz1 * LUT_D + iy ) * LUT_D + ix;
    int row11 = (iz1 * LUT_D + iy1) * LUT_D + ix;

    uint4 c00 = g_cells[row00];
    uint4 c01 = g_cells[row01];
    uint4 c10 = g_cells[row10];
    uint4 c11 = g_cells[row11];

    float3 v00 = lerp_cell(c00, fx);
    float3 v01 = lerp_cell(c01, fx);
    float3 v10 = lerp_cell(c10, fx);
    float3 v11 = lerp_cell(c11, fx);

    float3 v0, v1;
    v0.x = fmaf(fy, v01.x - v00.x, v00.x);
    v0.y = fmaf(fy, v01.y - v00.y, v00.y);
    v0.z = fmaf(fy, v01.z - v00.z, v00.z);
    v1.x = fmaf(fy, v11.x - v10.x, v10.x);
    v1.y = fmaf(fy, v11.y - v10.y, v10.y);
    v1.z = fmaf(fy, v11.z - v10.z, v10.z);

    r = fmaf(fz, v1.x - v0.x, v0.x);
    g = fmaf(fz, v1.y - v0.y, v0.y);
    b = fmaf(fz, v1.z - v0.z, v0.z);
}

__global__ void apply_lut_kernel(const float* __restrict__ img,
                                 float* __restrict__ out,
                                 int HW, int groups_per_img, int groups_total) {
    int t = blockIdx.x * blockDim.x + threadIdx.x;
    if (t >= groups_total) return;
    int b = t / groups_per_img;
    int q = (t - b * groups_per_img) * 4;

    const float* in_base = img + (size_t)b * 3 * HW + q;
    float* out_base = out + (size_t)b * 3 * HW + q;

    float4 xv = *reinterpret_cast<const float4*>(in_base);
    float4 yv = *reinterpret_cast<const float4*>(in_base + HW);
    float4 zv = *reinterpret_cast<const float4*>(in_base + 2 * HW);

    float xs[4] = {xv.x, xv.y, xv.z, xv.w};
    float ys[4] = {yv.x, yv.y, yv.z, yv.w};
    float zs[4] = {zv.x, zv.y, zv.z, zv.w};
    float rs[4], gs[4], bs[4];

#pragma unroll
    for (int p = 0; p < 4; p++) {
        sample_lut(xs[p], ys[p], zs[p], rs[p], gs[p], bs[p]);
    }

    float4 ro = make_float4(rs[0], rs[1], rs[2], rs[3]);
    float4 go = make_float4(gs[0], gs[1], gs[2], gs[3]);
    float4 bo = make_float4(bs[0], bs[1], bs[2], bs[3]);

    *reinterpret_cast<float4*>(out_base)          = ro;
    *reinterpret_cast<float4*>(out_base + HW)     = go;
    *reinterpret_cast<float4*>(out_base + 2 * HW) = bo;
}

extern "C" void kernel_launch(void* const* d_in, const int* in_sizes, int n_in,
                              void* d_out, int out_size) {
    const float* lut = (const float*)d_in[0];
    const float* img = (const float*)d_in[1];
    float* out = (float*)d_out;

    int img_elems = in_sizes[1];          // B * 3 * H * W
    const int B = 4;
    int HW = img_elems / (3 * B);         // 1080*1920 = 2,073,600
    int groups_per_img = HW / 4;
    int groups_total = B * groups_per_img;

    repack_kernel<<<(NCELL + 255) / 256, 256>>>(lut);
    apply_lut_kernel<<<(groups_total + 255) / 256, 256>>>(img, out, HW,
                                                          groups_per_img,
                                                          groups_total);
}

// round 2
// speedup vs baseline: 2.1690x; 2.1690x over previous
#include <cuda_runtime.h>
#include <cuda_fp16.h>

#define LUT_D 33
#define NCELL (LUT_D * LUT_D * LUT_D)   // 35937

// Expanded LUT: one 64B cell per (z,y,x) holding all 8 trilinear corners
// (clamped) x 3 channels in fp16: h[c*3+ch], c = dz*4+dy*2+dx.
// 24 halfs = 48B used, padded to 64B so a cell never spans a 128B line and
// the 3 LDG.128 chunks of one cell always hit the same L1 line.
static __device__ __align__(128) uint4 g_cells[NCELL * 4];   // 2.30 MB

__global__ void repack_kernel(const float* __restrict__ lut) {
    int i = blockIdx.x * blockDim.x + threadIdx.x;
    if (i >= NCELL) return;
    int x = i % LUT_D;
    int t = i / LUT_D;
    int y = t % LUT_D;
    int z = t / LUT_D;

    __half h[24];
#pragma unroll
    for (int c = 0; c < 8; c++) {
        int dz = (c >> 2) & 1, dy = (c >> 1) & 1, dx = c & 1;
        int zz = min(z + dz, LUT_D - 1);
        int yy = min(y + dy, LUT_D - 1);
        int xx = min(x + dx, LUT_D - 1);
        int idx = (zz * LUT_D + yy) * LUT_D + xx;
        h[c * 3 + 0] = __float2half_rn(lut[0 * NCELL + idx]);
        h[c * 3 + 1] = __float2half_rn(lut[1 * NCELL + idx]);
        h[c * 3 + 2] = __float2half_rn(lut[2 * NCELL + idx]);
    }

    const unsigned int* w = reinterpret_cast<const unsigned int*>(h);
    uint4 A = make_uint4(w[0], w[1], w[2], w[3]);
    uint4 B = make_uint4(w[4], w[5], w[6], w[7]);
    uint4 C = make_uint4(w[8], w[9], w[10], w[11]);
    g_cells[i * 4 + 0] = A;
    g_cells[i * 4 + 1] = B;
    g_cells[i * 4 + 2] = C;
    // g_cells[i*4+3] is padding, never read
}

__device__ __forceinline__ void sample_lut(float x, float y, float z,
                                           float& r, float& g, float& b) {
    const float S = 32.0f;
    x = fminf(fmaxf(x * S, 0.0f), S);
    y = fminf(fmaxf(y * S, 0.0f), S);
    z = fminf(fmaxf(z * S, 0.0f), S);
    int ix = (int)x;
    int iy = (int)y;
    int iz = (int)z;
    float fx = x - (float)ix;
    float fy = y - (float)iy;
    float fz = z - (float)iz;

    int base = ((iz * LUT_D + iy) * LUT_D + ix) * 4;
    uint4 A = g_cells[base + 0];
    uint4 B = g_cells[base + 1];
    uint4 C = g_cells[base + 2];

    float f[24];
    {
        float2 p;
        p = __half22float2(reinterpret_cast<const __half2&>(A.x)); f[0]=p.x;  f[1]=p.y;
        p = __half22float2(reinterpret_cast<const __half2&>(A.y)); f[2]=p.x;  f[3]=p.y;
        p = __half22float2(reinterpret_cast<const __half2&>(A.z)); f[4]=p.x;  f[5]=p.y;
        p = __half22float2(reinterpret_cast<const __half2&>(A.w)); f[6]=p.x;  f[7]=p.y;
        p = __half22float2(reinterpret_cast<const __half2&>(B.x)); f[8]=p.x;  f[9]=p.y;
        p = __half22float2(reinterpret_cast<const __half2&>(B.y)); f[10]=p.x; f[11]=p.y;
        p = __half22float2(reinterpret_cast<const __half2&>(B.z)); f[12]=p.x; f[13]=p.y;
        p = __half22float2(reinterpret_cast<const __half2&>(B.w)); f[14]=p.x; f[15]=p.y;
        p = __half22float2(reinterpret_cast<const __half2&>(C.x)); f[16]=p.x; f[17]=p.y;
        p = __half22float2(reinterpret_cast<const __half2&>(C.y)); f[18]=p.x; f[19]=p.y;
        p = __half22float2(reinterpret_cast<const __half2&>(C.z)); f[20]=p.x; f[21]=p.y;
        p = __half22float2(reinterpret_cast<const __half2&>(C.w)); f[22]=p.x; f[23]=p.y;
    }

    // x-lerp the 4 (dz,dy) corner pairs: pair j has corners 2j (dx=0), 2j+1 (dx=1)
    float vr[4], vg[4], vb[4];
#pragma unroll
    for (int j = 0; j < 4; j++) {
        vr[j] = fmaf(fx, f[6*j+3] - f[6*j+0], f[6*j+0]);
        vg[j] = fmaf(fx, f[6*j+4] - f[6*j+1], f[6*j+1]);
        vb[j] = fmaf(fx, f[6*j+5] - f[6*j+2], f[6*j+2]);
    }
    // y-lerp: j=0 (dz=0,dy=0) with j=1 (dz=0,dy=1); j=2 with j=3
    float u0r = fmaf(fy, vr[1] - vr[0], vr[0]);
    float u0g = fmaf(fy, vg[1] - vg[0], vg[0]);
    float u0b = fmaf(fy, vb[1] - vb[0], vb[0]);
    float u1r = fmaf(fy, vr[3] - vr[2], vr[2]);
    float u1g = fmaf(fy, vg[3] - vg[2], vg[2]);
    float u1b = fmaf(fy, vb[3] - vb[2], vb[2]);
    // z-lerp
    r = fmaf(fz, u1r - u0r, u0r);
    g = fmaf(fz, u1g - u0g, u0g);
    b = fmaf(fz, u1b - u0b, u0b);
}

__global__ __launch_bounds__(256)
void apply_lut_kernel(const float* __restrict__ img,
                      float* __restrict__ out,
                      int HW, int groups_per_img, int groups_total) {
    int t = blockIdx.x * blockDim.x + threadIdx.x;
    if (t >= groups_total) return;
    int b = t / groups_per_img;
    int q = (t - b * groups_per_img) * 2;

    const float* in_base = img + (size_t)b * 3 * HW + q;
    float* out_base = out + (size_t)b * 3 * HW + q;

    float2 xv = *reinterpret_cast<const float2*>(in_base);
    float2 yv = *reinterpret_cast<const float2*>(in_base + HW);
    float2 zv = *reinterpret_cast<const float2*>(in_base + 2 * HW);

    float r0, g0, b0, r1, g1, b1;
    sample_lut(xv.x, yv.x, zv.x, r0, g0, b0);
    sample_lut(xv.y, yv.y, zv.y, r1, g1, b1);

    *reinterpret_cast<float2*>(out_base)          = make_float2(r0, r1);
    *reinterpret_cast<float2*>(out_base + HW)     = make_float2(g0, g1);
    *reinterpret_cast<float2*>(out_base + 2 * HW) = make_float2(b0, b1);
}

extern "C" void kernel_launch(void* const* d_in, const int* in_sizes, int n_in,
                              void* d_out, int out_size) {
    const float* lut = (const float*)d_in[0];
    const float* img = (const float*)d_in[1];
    float* out = (float*)d_out;

    int img_elems = in_sizes[1];          // B * 3 * H * W
    const int B = 4;
    int HW = img_elems / (3 * B);         // 1080*1920
    int groups_per_img = HW / 2;
    int groups_total = B * groups_per_img;

    repack_kernel<<<(NCELL + 255) / 256, 256>>>(lut);
    apply_lut_kernel<<<(groups_total + 255) / 256, 256>>>(img, out, HW,
                                                          groups_per_img,
                                                          groups_total);
}

// round 3
// speedup vs baseline: 2.8506x; 1.3142x over previous
#include <cuda_runtime.h>
#include <cuda_fp16.h>

#define LUT_D 33
#define NCELL (LUT_D * LUT_D * LUT_D)   // 35937

// Packed LUT: one 32B cell per (z,y,x): 8 corner words, word c = dz*4+dy*2+dx:
//   bits [0:11)  r as round(v*2047)
//   bits [11:22) g as round(v*2047)
//   bits [22:32) b as round(v*1023)
// 32B-aligned -> both 16B chunks of a cell always share one 128B line.
static __device__ __align__(128) uint4 g_cells[NCELL * 2];   // 1.15 MB

__global__ void repack_kernel(const float* __restrict__ lut) {
    int i = blockIdx.x * blockDim.x + threadIdx.x;
    if (i >= NCELL) return;
    int x = i % LUT_D;
    int t = i / LUT_D;
    int y = t % LUT_D;
    int z = t / LUT_D;

    unsigned int w[8];
#pragma unroll
    for (int c = 0; c < 8; c++) {
        int dz = (c >> 2) & 1, dy = (c >> 1) & 1, dx = c & 1;
        int zz = min(z + dz, LUT_D - 1);
        int yy = min(y + dy, LUT_D - 1);
        int xx = min(x + dx, LUT_D - 1);
        int idx = (zz * LUT_D + yy) * LUT_D + xx;
        float r = lut[0 * NCELL + idx];
        float g = lut[1 * NCELL + idx];
        float b = lut[2 * NCELL + idx];
        unsigned int kr = (unsigned int)min(max(__float2int_rn(r * 2047.0f), 0), 2047);
        unsigned int kg = (unsigned int)min(max(__float2int_rn(g * 2047.0f), 0), 2047);
        unsigned int kb = (unsigned int)min(max(__float2int_rn(b * 1023.0f), 0), 1023);
        w[c] = kr | (kg << 11) | (kb << 22);
    }
    g_cells[i * 2 + 0] = make_uint4(w[0], w[1], w[2], w[3]);
    g_cells[i * 2 + 1] = make_uint4(w[4], w[5], w[6], w[7]);
}

// Mantissa-splice decode: returns 1.0f + k/2048 (exact).
__device__ __forceinline__ float dec_r(unsigned int w) {
    return __uint_as_float(((w << 12) & 0x007FF000u) | 0x3F800000u);
}
__device__ __forceinline__ float dec_g(unsigned int w) {
    return __uint_as_float(((w << 1) & 0x007FF000u) | 0x3F800000u);
}
__device__ __forceinline__ float dec_b(unsigned int w) {
    return __uint_as_float(((w >> 10) & 0x003FF000u) | 0x3F800000u);
}

struct F3 { float r, g, b; };

__device__ __forceinline__ F3 sample_lut(float x, float y, float z,
                                         const uint4& A, const uint4& B,
                                         float fx, float fy, float fz) {
    // corners c = dz*4+dy*2+dx; A = words 0..3, B = words 4..7
    unsigned int w0 = A.x, w1 = A.y, w2 = A.z, w3 = A.w;
    unsigned int w4 = B.x, w5 = B.y, w6 = B.z, w7 = B.w;

    // x-lerp (pairs: 0-1, 2-3, 4-5, 6-7)
    float r01 = fmaf(fx, dec_r(w1) - dec_r(w0), dec_r(w0));
    float g01 = fmaf(fx, dec_g(w1) - dec_g(w0), dec_g(w0));
    float b01 = fmaf(fx, dec_b(w1) - dec_b(w0), dec_b(w0));
    float r23 = fmaf(fx, dec_r(w3) - dec_r(w2), dec_r(w2));
    float g23 = fmaf(fx, dec_g(w3) - dec_g(w2), dec_g(w2));
    float b23 = fmaf(fx, dec_b(w3) - dec_b(w2), dec_b(w2));
    float r45 = fmaf(fx, dec_r(w5) - dec_r(w4), dec_r(w4));
    float g45 = fmaf(fx, dec_g(w5) - dec_g(w4), dec_g(w4));
    float b45 = fmaf(fx, dec_b(w5) - dec_b(w4), dec_b(w4));
    float r67 = fmaf(fx, dec_r(w7) - dec_r(w6), dec_r(w6));
    float g67 = fmaf(fx, dec_g(w7) - dec_g(w6), dec_g(w6));
    float b67 = fmaf(fx, dec_b(w7) - dec_b(w6), dec_b(w6));

    // y-lerp
    float r0 = fmaf(fy, r23 - r01, r01);
    float g0 = fmaf(fy, g23 - g01, g01);
    float b0 = fmaf(fy, b23 - b01, b01);
    float r1 = fmaf(fy, r67 - r45, r45);
    float g1 = fmaf(fy, g67 - g45, g45);
    float b1 = fmaf(fy, b67 - b45, b45);

    // z-lerp -> combo = 1 + value_scaled
    float rc = fmaf(fz, r1 - r0, r0);
    float gc = fmaf(fz, g1 - g0, g0);
    float bc = fmaf(fz, b1 - b0, b0);

    // remove +1 offset and rescale: value = (combo - 1) * (2048/K)
    const float SR = 2048.0f / 2047.0f;
    const float SB = 2048.0f / 1023.0f;
    F3 o;
    o.r = fmaf(rc, SR, -SR);
    o.g = fmaf(gc, SR, -SR);
    o.b = fmaf(bc, SB, -SB);
    return o;
}

__device__ __forceinline__ int cell_index(float x, float y, float z,
                                          float& fx, float& fy, float& fz) {
    const float S = 32.0f;
    x = fminf(fmaxf(x * S, 0.0f), S);
    y = fminf(fmaxf(y * S, 0.0f), S);
    z = fminf(fmaxf(z * S, 0.0f), S);
    int ix = (int)x;
    int iy = (int)y;
    int iz = (int)z;
    fx = x - (float)ix;
    fy = y - (float)iy;
    fz = z - (float)iz;
    return (iz * LUT_D + iy) * LUT_D + ix;
}

__global__ __launch_bounds__(256)
void apply_lut_kernel(const float* __restrict__ img,
                      float* __restrict__ out,
                      int HW, int groups_per_img, int groups_total) {
    int t = blockIdx.x * blockDim.x + threadIdx.x;
    if (t >= groups_total) return;
    int b = t / groups_per_img;
    int q = (t - b * groups_per_img) * 2;

    const float* in_base = img + (size_t)b * 3 * HW + q;
    float* out_base = out + (size_t)b * 3 * HW + q;

    float2 xv = *reinterpret_cast<const float2*>(in_base);
    float2 yv = *reinterpret_cast<const float2*>(in_base + HW);
    float2 zv = *reinterpret_cast<const float2*>(in_base + 2 * HW);

    // Compute both cell addresses first, then issue all 4 gathers (max MLP).
    float fx0, fy0, fz0, fx1, fy1, fz1;
    int c0 = cell_index(xv.x, yv.x, zv.x, fx0, fy0, fz0);
    int c1 = cell_index(xv.y, yv.y, zv.y, fx1, fy1, fz1);

    uint4 A0 = g_cells[c0 * 2 + 0];
    uint4 B0 = g_cells[c0 * 2 + 1];
    uint4 A1 = g_cells[c1 * 2 + 0];
    uint4 B1 = g_cells[c1 * 2 + 1];

    F3 p0 = sample_lut(xv.x, yv.x, zv.x, A0, B0, fx0, fy0, fz0);
    F3 p1 = sample_lut(xv.y, yv.y, zv.y, A1, B1, fx1, fy1, fz1);

    *reinterpret_cast<float2*>(out_base)          = make_float2(p0.r, p1.r);
    *reinterpret_cast<float2*>(out_base + HW)     = make_float2(p0.g, p1.g);
    *reinterpret_cast<float2*>(out_base + 2 * HW) = make_float2(p0.b, p1.b);
}

extern "C" void kernel_launch(void* const* d_in, const int* in_sizes, int n_in,
                              void* d_out, int out_size) {
    const float* lut = (const float*)d_in[0];
    const float* img = (const float*)d_in[1];
    float* out = (float*)d_out;

    int img_elems = in_sizes[1];          // B * 3 * H * W
    const int B = 4;
    int HW = img_elems / (3 * B);         // 1080*1920
    int groups_per_img = HW / 2;
    int groups_total = B * groups_per_img;

    repack_kernel<<<(NCELL + 255) / 256, 256>>>(lut);
    apply_lut_kernel<<<(groups_total + 255) / 256, 256>>>(img, out, HW,
                                                          groups_per_img,
                                                          groups_total);
}